// round 2
// baseline (speedup 1.0000x reference)
#include <cuda_runtime.h>

// GCN: 3 layers of  relu(adj @ (H @ W) + b)  (no relu on last layer)
// B=32 graphs, N=512 nodes, D=512 everywhere. All GEMMs are 512x512x512.
//
// Scratch buffers (allocation-free rule): __device__ globals.
static __device__ float g_bufS[32u * 512u * 512u];
static __device__ float g_bufH[32u * 512u * 512u];

#define BM 128
#define BN 128
#define BK 16
#define TM 8
#define TN 8

// C[b] = A[b] @ B[b] (+bias) (+relu). All matrices 512x512 row-major.
// strideB == 0 -> shared weight matrix across the batch.
template <bool RELU, bool BIAS>
__global__ __launch_bounds__(256, 2)
void gemm512(const float* __restrict__ Aall, const float* __restrict__ Ball,
             const float* __restrict__ bias, float* __restrict__ Call,
             long strideA, long strideB)
{
    constexpr int N = 512;
    constexpr int K = 512;

    const float* A = Aall + (long)blockIdx.z * strideA;
    const float* B = Ball + (long)blockIdx.z * strideB;
    float*       C = Call + (long)blockIdx.z * (long)512 * 512;

    __shared__ float As[BK][BM];
    __shared__ float Bs[BK][BN];

    const int tid = threadIdx.x;
    const int tx = tid % 16;          // 16 thread-cols
    const int ty = tid / 16;          // 16 thread-rows

    const int rowBlock = blockIdx.y * BM;
    const int colBlock = blockIdx.x * BN;

    // A-tile load mapping: 128x16 floats = 512 float4; 2 float4 per thread.
    const int aRow  = tid / 4;        // 0..63  (+64 for second load)
    const int aCol4 = tid % 4;        // float4 index within BK=16
    // B-tile load mapping: 16x128 floats = 512 float4; 2 float4 per thread.
    const int bRow  = tid / 32;       // 0..7   (+8 for second load)
    const int bCol4 = tid % 32;       // float4 index within BN=128

    float acc[TM][TN] = {};
    float ra[TM], rb[TN];

    for (int k0 = 0; k0 < K; k0 += BK) {
        // Load A tile (transposed into As[k][m] for coalesced compute reads)
        #pragma unroll
        for (int r = 0; r < 2; ++r) {
            const int row = aRow + r * 64;
            const float4 v = *(const float4*)(A + (long)(rowBlock + row) * K
                                                + k0 + aCol4 * 4);
            As[aCol4 * 4 + 0][row] = v.x;
            As[aCol4 * 4 + 1][row] = v.y;
            As[aCol4 * 4 + 2][row] = v.z;
            As[aCol4 * 4 + 3][row] = v.w;
        }
        // Load B tile (row-major direct)
        #pragma unroll
        for (int r = 0; r < 2; ++r) {
            const int row = bRow + r * 8;
            *(float4*)(&Bs[row][bCol4 * 4]) =
                *(const float4*)(B + (long)(k0 + row) * N + colBlock + bCol4 * 4);
        }
        __syncthreads();

        #pragma unroll
        for (int kk = 0; kk < BK; ++kk) {
            #pragma unroll
            for (int i = 0; i < TM; ++i) ra[i] = As[kk][ty * TM + i];
            #pragma unroll
            for (int j = 0; j < TN; ++j) rb[j] = Bs[kk][tx * TN + j];
            #pragma unroll
            for (int i = 0; i < TM; ++i)
                #pragma unroll
                for (int j = 0; j < TN; ++j)
                    acc[i][j] += ra[i] * rb[j];
        }
        __syncthreads();
    }

    // Epilogue
    #pragma unroll
    for (int i = 0; i < TM; ++i) {
        const int row = rowBlock + ty * TM + i;
        #pragma unroll
        for (int j = 0; j < TN; j += 4) {
            const int col = colBlock + tx * TN + j;
            float4 v = make_float4(acc[i][j], acc[i][j + 1],
                                   acc[i][j + 2], acc[i][j + 3]);
            if (BIAS) {
                v.x += bias[col + 0];
                v.y += bias[col + 1];
                v.z += bias[col + 2];
                v.w += bias[col + 3];
            }
            if (RELU) {
                v.x = fmaxf(v.x, 0.f);
                v.y = fmaxf(v.y, 0.f);
                v.z = fmaxf(v.z, 0.f);
                v.w = fmaxf(v.w, 0.f);
            }
            *(float4*)(C + (long)row * N + col) = v;
        }
    }
}

extern "C" void kernel_launch(void* const* d_in, const int* in_sizes, int n_in,
                              void* d_out, int out_size)
{
    const float* X   = (const float*)d_in[0];  // batch_graph [32,512,512]
    const float* adj = (const float*)d_in[1];  // adj         [32,512,512]
    const float* W0  = (const float*)d_in[2];
    const float* b0  = (const float*)d_in[3];
    const float* W1  = (const float*)d_in[4];
    const float* b1  = (const float*)d_in[5];
    const float* W2  = (const float*)d_in[6];
    const float* b2  = (const float*)d_in[7];
    float* out = (float*)d_out;

    float *S = nullptr, *H = nullptr;
    cudaGetSymbolAddress((void**)&S, g_bufS);
    cudaGetSymbolAddress((void**)&H, g_bufH);

    const long s = 512l * 512l;
    const dim3 grid(512 / BN, 512 / BM, 32);
    const dim3 block(256);

    // Layer 0
    gemm512<false, false><<<grid, block>>>(X,   W0, nullptr, S, s, 0);
    gemm512<true,  true ><<<grid, block>>>(adj, S,  b0,      H, s, s);
    // Layer 1
    gemm512<false, false><<<grid, block>>>(H,   W1, nullptr, S, s, 0);
    gemm512<true,  true ><<<grid, block>>>(adj, S,  b1,      H, s, s);
    // Layer 2 (no relu)
    gemm512<false, false><<<grid, block>>>(H,   W2, nullptr, S, s, 0);
    gemm512<false, true ><<<grid, block>>>(adj, S,  b2,      out, s, s);
}

// round 4
// speedup vs baseline: 2.2119x; 2.2119x over previous
#include <cuda_runtime.h>
#include <cuda_bf16.h>
#include <cstdint>

// ============================================================
// GCN via bf16-split (hi+lo) warp MMA (mma.sync m16n8k16, base sm target).
// Every GEMM computed as D[m,n] = sum_k A[m,k] * Bt[n,k]  (K-major both sides).
//   feature GEMM:  S^T[j,i] = sum_k Wt[j,k] * H[i,k]      (EPI=0, plain store)
//   adj GEMM:      H'[i,e]  = sum_k adj[i,k] * S^T[e,k]   (+bias, EPI=1 relu / 2)
// fp32 accuracy recovered with 3 MMA terms: hh + hl + lh (err ~2^-18).
// ============================================================

static __device__ float g_bufS[32u * 512u * 512u];   // S^T scratch
static __device__ float g_bufH[32u * 512u * 512u];   // H scratch
static __device__ float g_bufWt[3u * 512u * 512u];   // W^T x3

__device__ __forceinline__ uint32_t smem_u32(const void* p) {
    uint32_t a;
    asm("{ .reg .u64 t; cvta.to.shared.u64 t, %1; cvt.u32.u64 %0, t; }"
        : "=r"(a) : "l"(p));
    return a;
}

#define LDSM_X4(r0, r1, r2, r3, addr) \
    asm volatile("ldmatrix.sync.aligned.m8n8.x4.shared.b16 {%0,%1,%2,%3}, [%4];" \
                 : "=r"(r0), "=r"(r1), "=r"(r2), "=r"(r3) : "r"(addr))

__device__ __forceinline__ void mma16816(float* d, const uint32_t* a,
                                         uint32_t b0, uint32_t b1) {
    asm volatile(
        "mma.sync.aligned.m16n8k16.row.col.f32.bf16.bf16.f32 "
        "{%0,%1,%2,%3}, {%4,%5,%6,%7}, {%8,%9}, {%0,%1,%2,%3};"
        : "+f"(d[0]), "+f"(d[1]), "+f"(d[2]), "+f"(d[3])
        : "r"(a[0]), "r"(a[1]), "r"(a[2]), "r"(a[3]), "r"(b0), "r"(b1));
}

// smem tile: 128 rows x 32 bf16 (64B) padded to 80B stride -> conflict-free ldmatrix
static constexpr int TSTR = 80;
static constexpr int TSZ  = 128 * TSTR;          // 10240 B per tile
static constexpr int SMEM_BYTES = 4 * TSZ;       // Ahi, Alo, Bhi, Blo = 40KB

__device__ __forceinline__ void split_sts(float4 v, uint32_t dhi, uint32_t dlo) {
    __nv_bfloat162 h0 = __floats2bfloat162_rn(v.x, v.y);
    __nv_bfloat162 h1 = __floats2bfloat162_rn(v.z, v.w);
    float lx = v.x - __bfloat162float(h0.x);
    float ly = v.y - __bfloat162float(h0.y);
    float lz = v.z - __bfloat162float(h1.x);
    float lw = v.w - __bfloat162float(h1.y);
    __nv_bfloat162 l0 = __floats2bfloat162_rn(lx, ly);
    __nv_bfloat162 l1 = __floats2bfloat162_rn(lz, lw);
    uint32_t u0 = *(uint32_t*)&h0, u1 = *(uint32_t*)&h1;
    uint32_t w0 = *(uint32_t*)&l0, w1 = *(uint32_t*)&l1;
    asm volatile("st.shared.v2.b32 [%0], {%1,%2};" :: "r"(dhi), "r"(u0), "r"(u1) : "memory");
    asm volatile("st.shared.v2.b32 [%0], {%1,%2};" :: "r"(dlo), "r"(w0), "r"(w1) : "memory");
}

// EPI: 0 = plain store, 1 = bias+relu, 2 = bias
template <int EPI>
__global__ __launch_bounds__(256)
void hgemm(const float* __restrict__ Aall, const float* __restrict__ Btall,
           const float* __restrict__ bias, float* __restrict__ Call,
           long strideA, long strideBt)
{
    extern __shared__ char smem[];
    const uint32_t sA_hi = smem_u32(smem);
    const uint32_t sA_lo = sA_hi + TSZ;
    const uint32_t sB_hi = sA_hi + 2 * TSZ;
    const uint32_t sB_lo = sA_hi + 3 * TSZ;

    const int tid  = threadIdx.x;
    const int wid  = tid >> 5;
    const int lane = tid & 31;

    const long s = 512l * 512l;
    const float* A  = Aall  + (long)blockIdx.z * strideA;
    const float* Bt = Btall + (long)blockIdx.z * strideBt;
    float*       C  = Call  + (long)blockIdx.z * s;

    const int rowBlock = blockIdx.y * 128;
    const int colBlock = blockIdx.x * 128;

    const int wm = (wid >> 2) * 64;    // warp row offset (2 warps in M)
    const int wn = (wid & 3) * 32;     // warp col offset (4 warps in N)

    // per-thread load geometry: 4 float4 per 128x32 tile
    int lrow[4], lk4[4];
    #pragma unroll
    for (int i = 0; i < 4; ++i) {
        const int fi = tid + i * 256;
        lrow[i] = fi >> 3;
        lk4[i]  = fi & 7;
    }

    float acc[4][4][4] = {};
    float4 pa[4], pb[4];

    // ldmatrix base addresses (per-thread, reused every step)
    const uint32_t lmRow = lane & 15;
    const uint32_t lmCol = (lane >> 4) * 16;   // bytes
    uint32_t aAddr[4], bAddr[2][2];            // bAddr[hi/lo][tjj]
    #pragma unroll
    for (int ti = 0; ti < 4; ++ti)
        aAddr[ti] = (wm + ti * 16 + lmRow) * TSTR + lmCol;
    #pragma unroll
    for (int tjj = 0; tjj < 2; ++tjj) {
        bAddr[0][tjj] = sB_hi + (wn + tjj * 16 + lmRow) * TSTR + lmCol;
        bAddr[1][tjj] = sB_lo + (wn + tjj * 16 + lmRow) * TSTR + lmCol;
    }

    // prologue: load chunk 0
    #pragma unroll
    for (int i = 0; i < 4; ++i) {
        pa[i] = *(const float4*)(A  + (size_t)(rowBlock + lrow[i]) * 512 + lk4[i] * 4);
        pb[i] = *(const float4*)(Bt + (size_t)(colBlock + lrow[i]) * 512 + lk4[i] * 4);
    }
    #pragma unroll
    for (int i = 0; i < 4; ++i) {
        const uint32_t off = lrow[i] * TSTR + lk4[i] * 8;
        split_sts(pa[i], sA_hi + off, sA_lo + off);
        split_sts(pb[i], sB_hi + off, sB_lo + off);
    }
    __syncthreads();

    for (int c = 0; c < 16; ++c) {
        // prefetch next chunk into registers
        if (c < 15) {
            const int k0 = (c + 1) * 32;
            #pragma unroll
            for (int i = 0; i < 4; ++i) {
                pa[i] = *(const float4*)(A  + (size_t)(rowBlock + lrow[i]) * 512 + k0 + lk4[i] * 4);
                pb[i] = *(const float4*)(Bt + (size_t)(colBlock + lrow[i]) * 512 + k0 + lk4[i] * 4);
            }
        }

        // compute 2 x k16 from smem
        #pragma unroll
        for (int kk = 0; kk < 2; ++kk) {
            const uint32_t kOff = kk * 32;   // 16 bf16 = 32B
            uint32_t af[4][4], bh[2][4], bl[2][4];
            #pragma unroll
            for (int tjj = 0; tjj < 2; ++tjj) {
                LDSM_X4(bh[tjj][0], bh[tjj][1], bh[tjj][2], bh[tjj][3],
                        bAddr[0][tjj] + kOff);
                LDSM_X4(bl[tjj][0], bl[tjj][1], bl[tjj][2], bl[tjj][3],
                        bAddr[1][tjj] + kOff);
            }
            #pragma unroll
            for (int ti = 0; ti < 4; ++ti)
                LDSM_X4(af[ti][0], af[ti][1], af[ti][2], af[ti][3],
                        sA_hi + aAddr[ti] + kOff);
            // hh
            #pragma unroll
            for (int ti = 0; ti < 4; ++ti)
                #pragma unroll
                for (int tj = 0; tj < 4; ++tj)
                    mma16816(acc[ti][tj], af[ti],
                             bh[tj >> 1][tj & 1], bh[tj >> 1][2 + (tj & 1)]);
            // hl
            #pragma unroll
            for (int ti = 0; ti < 4; ++ti)
                #pragma unroll
                for (int tj = 0; tj < 4; ++tj)
                    mma16816(acc[ti][tj], af[ti],
                             bl[tj >> 1][tj & 1], bl[tj >> 1][2 + (tj & 1)]);
            // lh (A lo overwrites A hi frags)
            #pragma unroll
            for (int ti = 0; ti < 4; ++ti)
                LDSM_X4(af[ti][0], af[ti][1], af[ti][2], af[ti][3],
                        sA_lo + aAddr[ti] + kOff);
            #pragma unroll
            for (int ti = 0; ti < 4; ++ti)
                #pragma unroll
                for (int tj = 0; tj < 4; ++tj)
                    mma16816(acc[ti][tj], af[ti],
                             bh[tj >> 1][tj & 1], bh[tj >> 1][2 + (tj & 1)]);
        }
        __syncthreads();

        if (c < 15) {
            #pragma unroll
            for (int i = 0; i < 4; ++i) {
                const uint32_t off = lrow[i] * TSTR + lk4[i] * 8;
                split_sts(pa[i], sA_hi + off, sA_lo + off);
                split_sts(pb[i], sB_hi + off, sB_lo + off);
            }
            __syncthreads();
        }
    }

    // epilogue: direct register -> global stores
    #pragma unroll
    for (int ti = 0; ti < 4; ++ti) {
        const int m0 = rowBlock + wm + ti * 16 + (lane >> 2);
        #pragma unroll
        for (int tj = 0; tj < 4; ++tj) {
            const int n0 = colBlock + wn + tj * 8 + (lane & 3) * 2;
            float2 v0 = make_float2(acc[ti][tj][0], acc[ti][tj][1]);
            float2 v1 = make_float2(acc[ti][tj][2], acc[ti][tj][3]);
            if (EPI != 0) {
                const float bx = __ldg(bias + n0), by = __ldg(bias + n0 + 1);
                v0.x += bx; v0.y += by; v1.x += bx; v1.y += by;
                if (EPI == 1) {
                    v0.x = fmaxf(v0.x, 0.f); v0.y = fmaxf(v0.y, 0.f);
                    v1.x = fmaxf(v1.x, 0.f); v1.y = fmaxf(v1.y, 0.f);
                }
            }
            *(float2*)(C + (size_t)m0 * 512 + n0)       = v0;
            *(float2*)(C + (size_t)(m0 + 8) * 512 + n0) = v1;
        }
    }
}

// 512x512 transpose for the weight matrices
__global__ void transpose512(const float* __restrict__ in, float* __restrict__ out)
{
    __shared__ float t[32][33];
    const int bx = blockIdx.x * 32, by = blockIdx.y * 32;
    const int x = threadIdx.x, y = threadIdx.y;   // 32x8
    #pragma unroll
    for (int j = 0; j < 32; j += 8)
        t[y + j][x] = in[(size_t)(by + y + j) * 512 + bx + x];
    __syncthreads();
    #pragma unroll
    for (int j = 0; j < 32; j += 8)
        out[(size_t)(bx + y + j) * 512 + by + x] = t[x][y + j];
}

extern "C" void kernel_launch(void* const* d_in, const int* in_sizes, int n_in,
                              void* d_out, int out_size)
{
    const float* X   = (const float*)d_in[0];
    const float* adj = (const float*)d_in[1];
    const float* W0  = (const float*)d_in[2];
    const float* b0  = (const float*)d_in[3];
    const float* W1  = (const float*)d_in[4];
    const float* b1  = (const float*)d_in[5];
    const float* W2  = (const float*)d_in[6];
    const float* b2  = (const float*)d_in[7];
    float* out = (float*)d_out;

    float *S, *H, *Wt;
    cudaGetSymbolAddress((void**)&S,  g_bufS);
    cudaGetSymbolAddress((void**)&H,  g_bufH);
    cudaGetSymbolAddress((void**)&Wt, g_bufWt);

    cudaFuncSetAttribute(hgemm<0>, cudaFuncAttributeMaxDynamicSharedMemorySize, SMEM_BYTES);
    cudaFuncSetAttribute(hgemm<1>, cudaFuncAttributeMaxDynamicSharedMemorySize, SMEM_BYTES);
    cudaFuncSetAttribute(hgemm<2>, cudaFuncAttributeMaxDynamicSharedMemorySize, SMEM_BYTES);

    const long s = 512l * 512l;
    const dim3 tgrid(16, 16), tblk(32, 8);
    transpose512<<<tgrid, tblk>>>(W0, Wt + 0 * s);
    transpose512<<<tgrid, tblk>>>(W1, Wt + 1 * s);
    transpose512<<<tgrid, tblk>>>(W2, Wt + 2 * s);

    const dim3 grid(4, 4, 32), blk(256);
    // Layer 0:  S^T = (X @ W0)^T  via  Wt0 x X ;  H = relu(adj @ S + b0)
    hgemm<0><<<grid, blk, SMEM_BYTES>>>(Wt + 0 * s, X,  nullptr, S, 0, s);
    hgemm<1><<<grid, blk, SMEM_BYTES>>>(adj,        S,  b0,      H, s, s);
    // Layer 1
    hgemm<0><<<grid, blk, SMEM_BYTES>>>(Wt + 1 * s, H,  nullptr, S, 0, s);
    hgemm<1><<<grid, blk, SMEM_BYTES>>>(adj,        S,  b1,      H, s, s);
    // Layer 2 (no relu)
    hgemm<0><<<grid, blk, SMEM_BYTES>>>(Wt + 2 * s, H,  nullptr, S, 0, s);
    hgemm<2><<<grid, blk, SMEM_BYTES>>>(adj,        S,  b2,      out, s, s);
}

// round 6
// speedup vs baseline: 2.3982x; 1.0842x over previous
#include <cuda_runtime.h>
#include <cuda_bf16.h>
#include <cstdint>

// ============================================================
// GCN via bf16-split (hi+lo) warp MMA, cp.async 3-stage pipeline.
// All operands pre-split to bf16 hi/lo in GMEM; GEMM epilogues emit
// the next GEMM's hi/lo operands directly (no fp32 intermediates).
//   feature GEMM:  S^T[j,i] = sum_k Wt[j,k] * H[i,k]   (EPI=0)
//   adj GEMM:      H'[i,e]  = sum_k adj[i,k]* S^T[e,k] (EPI=1 relu, EPI=2 last)
// 3 MMA terms per fp32 product: hh + hl + lh  (err ~2^-18).
// ============================================================

static constexpr unsigned NE = 32u * 512u * 512u;     // 8M elems

static __device__ __nv_bfloat16 g_Xhi[NE],  g_Xlo[NE];
static __device__ __nv_bfloat16 g_Jhi[NE],  g_Jlo[NE];    // adj split
static __device__ __nv_bfloat16 g_Shi[NE],  g_Slo[NE];
static __device__ __nv_bfloat16 g_Hhi[NE],  g_Hlo[NE];
static __device__ __nv_bfloat16 g_Wthi[3u * 512u * 512u], g_Wtlo[3u * 512u * 512u];

__device__ __forceinline__ uint32_t smem_u32(const void* p) {
    uint32_t a;
    asm("{ .reg .u64 t; cvta.to.shared.u64 t, %1; cvt.u32.u64 %0, t; }"
        : "=r"(a) : "l"(p));
    return a;
}

#define LDSM_X4(r0, r1, r2, r3, addr) \
    asm volatile("ldmatrix.sync.aligned.m8n8.x4.shared.b16 {%0,%1,%2,%3}, [%4];" \
                 : "=r"(r0), "=r"(r1), "=r"(r2), "=r"(r3) : "r"(addr))

#define CP_ASYNC16(dst, src) \
    asm volatile("cp.async.cg.shared.global [%0], [%1], 16;" \
                 :: "r"(dst), "l"(src) : "memory")
#define CP_COMMIT() asm volatile("cp.async.commit_group;" ::: "memory")
#define CP_WAIT(n)  asm volatile("cp.async.wait_group %0;" :: "n"(n) : "memory")

__device__ __forceinline__ void mma16816(float* d, const uint32_t* a,
                                         uint32_t b0, uint32_t b1) {
    asm volatile(
        "mma.sync.aligned.m16n8k16.row.col.f32.bf16.bf16.f32 "
        "{%0,%1,%2,%3}, {%4,%5,%6,%7}, {%8,%9}, {%0,%1,%2,%3};"
        : "+f"(d[0]), "+f"(d[1]), "+f"(d[2]), "+f"(d[3])
        : "r"(a[0]), "r"(a[1]), "r"(a[2]), "r"(a[3]), "r"(b0), "r"(b1));
}

// smem tile: 128 rows x 32 bf16 = 64B/row, XOR swizzle on 16B chunks:
//   q' = q ^ ((row>>1)&3)   -> conflict-free ldmatrix & stores
static constexpr int TILE  = 128 * 64;           // 8KB
static constexpr int OFF_AH = 0, OFF_AL = TILE, OFF_BH = 2*TILE, OFF_BL = 3*TILE;
static constexpr int STAGE = 4 * TILE;           // 32KB
static constexpr int NSTG  = 3;
static constexpr int SMEM_BYTES = NSTG * STAGE;  // 96KB

__device__ __forceinline__ uint32_t sw_off(int row, int q) {
    return (uint32_t)row * 64u + (uint32_t)((q ^ ((row >> 1) & 3)) << 4);
}

// EPI: 0 = store hi/lo, 1 = bias+relu -> hi/lo, 2 = bias -> fp32
template <int EPI>
__global__ __launch_bounds__(256, 2)
void hgemm(const __nv_bfloat16* __restrict__ Ahi, const __nv_bfloat16* __restrict__ Alo,
           const __nv_bfloat16* __restrict__ Bhi, const __nv_bfloat16* __restrict__ Blo,
           const float* __restrict__ bias,
           float* __restrict__ Cf,
           __nv_bfloat16* __restrict__ Chi, __nv_bfloat16* __restrict__ Clo,
           long strideA, long strideB)
{
    extern __shared__ char smem[];
    const uint32_t sb = smem_u32(smem);
    const int tid  = threadIdx.x;
    const int wid  = tid >> 5;
    const int lane = tid & 31;

    const long s = 512l * 512l;
    const size_t offA = (size_t)blockIdx.z * strideA;
    const size_t offB = (size_t)blockIdx.z * strideB;

    const int rowBlock = blockIdx.y * 128;
    const int colBlock = blockIdx.x * 128;

    const int wm = (wid >> 2) * 64;
    const int wn = (wid & 3) * 32;

    // cp.async geometry: two (row, q) pairs per thread per tile
    const int cRow0 = tid >> 2;            // 0..63
    const int cQ    = tid & 3;
    const uint32_t d0 = sw_off(cRow0, cQ);
    const uint32_t d1 = sw_off(cRow0 + 64, cQ);
    const size_t gA0 = offA + (size_t)(rowBlock + cRow0) * 512 + cQ * 8;
    const size_t gA1 = gA0 + 64 * 512;
    const size_t gB0 = offB + (size_t)(colBlock + cRow0) * 512 + cQ * 8;
    const size_t gB1 = gB0 + 64 * 512;

    auto issue = [&](int c) {
        const uint32_t st = sb + (uint32_t)(c % NSTG) * STAGE;
        const int k0 = c * 32;
        CP_ASYNC16(st + OFF_AH + d0, Ahi + gA0 + k0);
        CP_ASYNC16(st + OFF_AH + d1, Ahi + gA1 + k0);
        CP_ASYNC16(st + OFF_AL + d0, Alo + gA0 + k0);
        CP_ASYNC16(st + OFF_AL + d1, Alo + gA1 + k0);
        CP_ASYNC16(st + OFF_BH + d0, Bhi + gB0 + k0);
        CP_ASYNC16(st + OFF_BH + d1, Bhi + gB1 + k0);
        CP_ASYNC16(st + OFF_BL + d0, Blo + gB0 + k0);
        CP_ASYNC16(st + OFF_BL + d1, Blo + gB1 + k0);
        CP_COMMIT();
    };

    // ldmatrix geometry
    const int lmRow = lane & 15;
    const int lmQ   = lane >> 4;           // 0/1; +2 for kk=1
    uint32_t aRow[4], bRow[2];
    int aXr[4], bXr[2];
    #pragma unroll
    for (int ti = 0; ti < 4; ++ti) {
        const int r = wm + ti * 16 + lmRow;
        aRow[ti] = (uint32_t)r * 64u;
        aXr[ti]  = (r >> 1) & 3;
    }
    #pragma unroll
    for (int tjj = 0; tjj < 2; ++tjj) {
        const int r = wn + tjj * 16 + lmRow;
        bRow[tjj] = (uint32_t)r * 64u;
        bXr[tjj]  = (r >> 1) & 3;
    }

    float acc[4][4][4] = {};

    issue(0);
    issue(1);

    for (int c = 0; c < 16; ++c) {
        if (c == 15) { CP_WAIT(0); } else { CP_WAIT(1); }
        __syncthreads();
        if (c + 2 < 16) issue(c + 2);

        const uint32_t st = sb + (uint32_t)(c % NSTG) * STAGE;

        #pragma unroll
        for (int kk = 0; kk < 2; ++kk) {
            const int q = lmQ + kk * 2;
            uint32_t af[4][4], bh[2][4], bl[2][4];
            #pragma unroll
            for (int tjj = 0; tjj < 2; ++tjj) {
                const uint32_t sw = (uint32_t)((q ^ bXr[tjj]) << 4);
                LDSM_X4(bh[tjj][0], bh[tjj][1], bh[tjj][2], bh[tjj][3],
                        st + OFF_BH + bRow[tjj] + sw);
                LDSM_X4(bl[tjj][0], bl[tjj][1], bl[tjj][2], bl[tjj][3],
                        st + OFF_BL + bRow[tjj] + sw);
            }
            #pragma unroll
            for (int ti = 0; ti < 4; ++ti) {
                const uint32_t sw = (uint32_t)((q ^ aXr[ti]) << 4);
                LDSM_X4(af[ti][0], af[ti][1], af[ti][2], af[ti][3],
                        st + OFF_AH + aRow[ti] + sw);
            }
            #pragma unroll
            for (int ti = 0; ti < 4; ++ti)
                #pragma unroll
                for (int tj = 0; tj < 4; ++tj)
                    mma16816(acc[ti][tj], af[ti],
                             bh[tj >> 1][tj & 1], bh[tj >> 1][2 + (tj & 1)]);
            #pragma unroll
            for (int ti = 0; ti < 4; ++ti)
                #pragma unroll
                for (int tj = 0; tj < 4; ++tj)
                    mma16816(acc[ti][tj], af[ti],
                             bl[tj >> 1][tj & 1], bl[tj >> 1][2 + (tj & 1)]);
            #pragma unroll
            for (int ti = 0; ti < 4; ++ti) {
                const uint32_t sw = (uint32_t)((q ^ aXr[ti]) << 4);
                LDSM_X4(af[ti][0], af[ti][1], af[ti][2], af[ti][3],
                        st + OFF_AL + aRow[ti] + sw);
            }
            #pragma unroll
            for (int ti = 0; ti < 4; ++ti)
                #pragma unroll
                for (int tj = 0; tj < 4; ++tj)
                    mma16816(acc[ti][tj], af[ti],
                             bh[tj >> 1][tj & 1], bh[tj >> 1][2 + (tj & 1)]);
        }
    }

    // epilogue
    const size_t offC = (size_t)blockIdx.z * s;
    #pragma unroll
    for (int ti = 0; ti < 4; ++ti) {
        const int m0 = rowBlock + wm + ti * 16 + (lane >> 2);
        #pragma unroll
        for (int tj = 0; tj < 4; ++tj) {
            const int n0 = colBlock + wn + tj * 8 + (lane & 3) * 2;
            float2 v0 = make_float2(acc[ti][tj][0], acc[ti][tj][1]);
            float2 v1 = make_float2(acc[ti][tj][2], acc[ti][tj][3]);
            if (EPI != 0) {
                const float bx = __ldg(bias + n0), by = __ldg(bias + n0 + 1);
                v0.x += bx; v0.y += by; v1.x += bx; v1.y += by;
                if (EPI == 1) {
                    v0.x = fmaxf(v0.x, 0.f); v0.y = fmaxf(v0.y, 0.f);
                    v1.x = fmaxf(v1.x, 0.f); v1.y = fmaxf(v1.y, 0.f);
                }
            }
            const size_t p0 = offC + (size_t)m0 * 512 + n0;
            const size_t p1 = p0 + 8 * 512;
            if (EPI == 2) {
                *(float2*)(Cf + p0) = v0;
                *(float2*)(Cf + p1) = v1;
            } else {
                __nv_bfloat162 h0 = __floats2bfloat162_rn(v0.x, v0.y);
                __nv_bfloat162 h1 = __floats2bfloat162_rn(v1.x, v1.y);
                __nv_bfloat162 l0 = __floats2bfloat162_rn(
                    v0.x - __bfloat162float(h0.x), v0.y - __bfloat162float(h0.y));
                __nv_bfloat162 l1 = __floats2bfloat162_rn(
                    v1.x - __bfloat162float(h1.x), v1.y - __bfloat162float(h1.y));
                *(uint32_t*)(Chi + p0) = *(uint32_t*)&h0;
                *(uint32_t*)(Chi + p1) = *(uint32_t*)&h1;
                *(uint32_t*)(Clo + p0) = *(uint32_t*)&l0;
                *(uint32_t*)(Clo + p1) = *(uint32_t*)&l1;
            }
        }
    }
}

// split fp32 -> bf16 hi/lo (vectorized)
__global__ __launch_bounds__(256)
void split_f32(const float* __restrict__ in,
               __nv_bfloat16* __restrict__ hi, __nv_bfloat16* __restrict__ lo,
               int n4)
{
    const int i = blockIdx.x * blockDim.x + threadIdx.x;
    if (i >= n4) return;
    float4 v = ((const float4*)in)[i];
    __nv_bfloat162 h0 = __floats2bfloat162_rn(v.x, v.y);
    __nv_bfloat162 h1 = __floats2bfloat162_rn(v.z, v.w);
    __nv_bfloat162 l0 = __floats2bfloat162_rn(v.x - __bfloat162float(h0.x),
                                              v.y - __bfloat162float(h0.y));
    __nv_bfloat162 l1 = __floats2bfloat162_rn(v.z - __bfloat162float(h1.x),
                                              v.w - __bfloat162float(h1.y));
    uint2 uh = make_uint2(*(uint32_t*)&h0, *(uint32_t*)&h1);
    uint2 ul = make_uint2(*(uint32_t*)&l0, *(uint32_t*)&l1);
    ((uint2*)hi)[i] = uh;
    ((uint2*)lo)[i] = ul;
}

// transpose 512x512 fp32 -> bf16 hi/lo (for weights)
__global__ void transpose_split512(const float* __restrict__ in,
                                   __nv_bfloat16* __restrict__ hi,
                                   __nv_bfloat16* __restrict__ lo)
{
    __shared__ float t[32][33];
    const int bx = blockIdx.x * 32, by = blockIdx.y * 32;
    const int x = threadIdx.x, y = threadIdx.y;   // 32x8
    #pragma unroll
    for (int j = 0; j < 32; j += 8)
        t[y + j][x] = in[(size_t)(by + y + j) * 512 + bx + x];
    __syncthreads();
    #pragma unroll
    for (int j = 0; j < 32; j += 8) {
        const float v = t[x][y + j];
        const size_t p = (size_t)(bx + y + j) * 512 + by + x;
        const __nv_bfloat16 h = __float2bfloat16_rn(v);
        hi[p] = h;
        lo[p] = __float2bfloat16_rn(v - __bfloat162float(h));
    }
}

extern "C" void kernel_launch(void* const* d_in, const int* in_sizes, int n_in,
                              void* d_out, int out_size)
{
    const float* X   = (const float*)d_in[0];
    const float* adj = (const float*)d_in[1];
    const float* W0  = (const float*)d_in[2];
    const float* b0  = (const float*)d_in[3];
    const float* W1  = (const float*)d_in[4];
    const float* b1  = (const float*)d_in[5];
    const float* W2  = (const float*)d_in[6];
    const float* b2  = (const float*)d_in[7];
    float* out = (float*)d_out;

    __nv_bfloat16 *Xhi, *Xlo, *Jhi, *Jlo, *Shi, *Slo, *Hhi, *Hlo, *Wthi, *Wtlo;
    cudaGetSymbolAddress((void**)&Xhi, g_Xhi);  cudaGetSymbolAddress((void**)&Xlo, g_Xlo);
    cudaGetSymbolAddress((void**)&Jhi, g_Jhi);  cudaGetSymbolAddress((void**)&Jlo, g_Jlo);
    cudaGetSymbolAddress((void**)&Shi, g_Shi);  cudaGetSymbolAddress((void**)&Slo, g_Slo);
    cudaGetSymbolAddress((void**)&Hhi, g_Hhi);  cudaGetSymbolAddress((void**)&Hlo, g_Hlo);
    cudaGetSymbolAddress((void**)&Wthi, g_Wthi); cudaGetSymbolAddress((void**)&Wtlo, g_Wtlo);

    cudaFuncSetAttribute(hgemm<0>, cudaFuncAttributeMaxDynamicSharedMemorySize, SMEM_BYTES);
    cudaFuncSetAttribute(hgemm<1>, cudaFuncAttributeMaxDynamicSharedMemorySize, SMEM_BYTES);
    cudaFuncSetAttribute(hgemm<2>, cudaFuncAttributeMaxDynamicSharedMemorySize, SMEM_BYTES);

    const long s = 512l * 512l;
    const int n4 = (int)(NE / 4);
    split_f32<<<(n4 + 255) / 256, 256>>>(X,   Xhi, Xlo, n4);
    split_f32<<<(n4 + 255) / 256, 256>>>(adj, Jhi, Jlo, n4);
    const dim3 tgrid(16, 16), tblk(32, 8);
    transpose_split512<<<tgrid, tblk>>>(W0, Wthi + 0 * s, Wtlo + 0 * s);
    transpose_split512<<<tgrid, tblk>>>(W1, Wthi + 1 * s, Wtlo + 1 * s);
    transpose_split512<<<tgrid, tblk>>>(W2, Wthi + 2 * s, Wtlo + 2 * s);

    const dim3 grid(4, 4, 32), blk(256);
    // Layer 0:  S^T = (X @ W0)^T ;  H = relu(adj @ S + b0)
    hgemm<0><<<grid, blk, SMEM_BYTES>>>(Wthi + 0*s, Wtlo + 0*s, Xhi, Xlo,
                                        nullptr, nullptr, Shi, Slo, 0, s);
    hgemm<1><<<grid, blk, SMEM_BYTES>>>(Jhi, Jlo, Shi, Slo,
                                        b0, nullptr, Hhi, Hlo, s, s);
    // Layer 1
    hgemm<0><<<grid, blk, SMEM_BYTES>>>(Wthi + 1*s, Wtlo + 1*s, Hhi, Hlo,
                                        nullptr, nullptr, Shi, Slo, 0, s);
    hgemm<1><<<grid, blk, SMEM_BYTES>>>(Jhi, Jlo, Shi, Slo,
                                        b1, nullptr, Hhi, Hlo, s, s);
    // Layer 2 (no relu, fp32 out)
    hgemm<0><<<grid, blk, SMEM_BYTES>>>(Wthi + 2*s, Wtlo + 2*s, Hhi, Hlo,
                                        nullptr, nullptr, Shi, Slo, 0, s);
    hgemm<2><<<grid, blk, SMEM_BYTES>>>(Jhi, Jlo, Shi, Slo,
                                        b2, out, nullptr, nullptr, s, s);
}